// round 7
// baseline (speedup 1.0000x reference)
#include <cuda_runtime.h>
#include <cuda_bf16.h>
#include <cstdint>

// Shapes (fixed): B=2, S=2048, D=1024, H=16, d=64
// head h of batch b = contiguous block (b*2048 + h*128)*1024 viewed as [2048,64] row-major
// d_out = [ proj : 4194304 f32 ][ attn : 134217728 f32 ]

#define PROJ_ELEMS 4194304LL
#define HEAD_STRIDE 131072LL
#define ATTN_STRIDE 4194304LL

// ---------------- persistent bf16 split buffers (device globals) ----------------
__device__ __nv_bfloat16 g_preh[12582912], g_prel[12582912];   // pre_q|pre_k|pre_v
__device__ __nv_bfloat16 g_Wh[3145728],   g_Wl[3145728];       // Wq|Wk|Wv
__device__ __nv_bfloat16 g_Woh[1048576],  g_Wol[1048576];
__device__ float         g_bias3[3072];                        // bq|bk|bv
__device__ __nv_bfloat16 g_QKVh[12582912], g_QKVl[12582912];   // Q|K|V (hi/lo)
__device__ __nv_bfloat16 g_Pb[134217728];                      // attn in bf16
__device__ __nv_bfloat16 g_Oh[4194304],   g_Ol[4194304];

// ---------------- helpers ----------------
__device__ __forceinline__ uint32_t smem_u32(const void* p) {
    return (uint32_t)__cvta_generic_to_shared(p);
}
__device__ __forceinline__ void cpa16(__nv_bfloat16* s, const __nv_bfloat16* g) {
    asm volatile("cp.async.cg.shared.global [%0], [%1], 16;"
                 :: "r"(smem_u32(s)), "l"(__cvta_generic_to_global(g)));
}
__device__ __forceinline__ void cp_commit() { asm volatile("cp.async.commit_group;"); }
template<int NW> __device__ __forceinline__ void cp_wait() {
    asm volatile("cp.async.wait_group %0;" :: "n"(NW));
}
__device__ __forceinline__ void ldmx4(uint32_t& r0, uint32_t& r1, uint32_t& r2, uint32_t& r3,
                                      uint32_t addr) {
    asm volatile("ldmatrix.sync.aligned.m8n8.x4.shared.b16 {%0,%1,%2,%3}, [%4];"
                 : "=r"(r0), "=r"(r1), "=r"(r2), "=r"(r3) : "r"(addr));
}
__device__ __forceinline__ void mma16(float* c, const uint32_t* a, const uint32_t* b) {
    asm volatile(
        "mma.sync.aligned.m16n8k16.row.col.f32.bf16.bf16.f32 "
        "{%0,%1,%2,%3},{%4,%5,%6,%7},{%8,%9},{%0,%1,%2,%3};"
        : "+f"(c[0]), "+f"(c[1]), "+f"(c[2]), "+f"(c[3])
        : "r"(a[0]), "r"(a[1]), "r"(a[2]), "r"(a[3]), "r"(b[0]), "r"(b[1]));
}
__device__ __forceinline__ void store_split2(__nv_bfloat16* h, __nv_bfloat16* l,
                                             float a, float b) {
    __nv_bfloat16 ha = __float2bfloat16(a), hb = __float2bfloat16(b);
    __nv_bfloat16 la = __float2bfloat16(a - __bfloat162float(ha));
    __nv_bfloat16 lb = __float2bfloat16(b - __bfloat162float(hb));
    __nv_bfloat162 hp; hp.x = ha; hp.y = hb;
    __nv_bfloat162 lp; lp.x = la; lp.y = lb;
    *(__nv_bfloat162*)h = hp;
    *(__nv_bfloat162*)l = lp;
}

#define SPAD 40   // smem row stride in bf16 (32 data + 8 pad) -> conflict-free ldmatrix

// ---------------------------------------------------------------------------
// prep: split fp32 -> bf16 hi/lo (vectorized), and bias gather
// ---------------------------------------------------------------------------
__global__ void splitk(const float4* __restrict__ x,
                       __nv_bfloat16* __restrict__ h, __nv_bfloat16* __restrict__ l, int n4)
{
    int i = blockIdx.x * blockDim.x + threadIdx.x;
    if (i >= n4) return;
    float4 v = x[i];
    float vs[4] = {v.x, v.y, v.z, v.w};
    __nv_bfloat16 hh[4], ll[4];
    #pragma unroll
    for (int c = 0; c < 4; c++) {
        hh[c] = __float2bfloat16(vs[c]);
        ll[c] = __float2bfloat16(vs[c] - __bfloat162float(hh[c]));
    }
    __nv_bfloat162 h0; h0.x = hh[0]; h0.y = hh[1];
    __nv_bfloat162 h1; h1.x = hh[2]; h1.y = hh[3];
    __nv_bfloat162 l0; l0.x = ll[0]; l0.y = ll[1];
    __nv_bfloat162 l1; l1.x = ll[2]; l1.y = ll[3];
    *(__nv_bfloat162*)(h + 4 * i)     = h0;
    *(__nv_bfloat162*)(h + 4 * i + 2) = h1;
    *(__nv_bfloat162*)(l + 4 * i)     = l0;
    *(__nv_bfloat162*)(l + 4 * i + 2) = l1;
}

__global__ void biascopy(const float* __restrict__ bq, const float* __restrict__ bk,
                         const float* __restrict__ bv, float* __restrict__ dst)
{
    int i = blockIdx.x * blockDim.x + threadIdx.x;
    if (i < 1024) { dst[i] = bq[i]; dst[1024 + i] = bk[i]; dst[2048 + i] = bv[i]; }
}

// ---------------------------------------------------------------------------
// gemm3: 3-pass split-bf16 NT GEMM, cp.async 2-stage pipelined.
//   C[m,n] = alpha * sum_k (Ah+Al)[m,k]*(Bh+Bl)[n,k] (+bias[n])   [lo*lo dropped]
//   A,B bf16 row-major K-contiguous. Block 128x128, BK=32, 256 thr, warp 64x32.
//   EPI=0: fp32 C (+bias).  EPI=1: split bf16 (Ch,Cl) (+bias).
// dynamic smem = 2 stages * 4 matrices * 128*SPAD bf16 = 81920 B
// ---------------------------------------------------------------------------
template<int EPI>
__global__ __launch_bounds__(256) void gemm3(
    const __nv_bfloat16* __restrict__ Ah, const __nv_bfloat16* __restrict__ Al,
    const __nv_bfloat16* __restrict__ Bh, const __nv_bfloat16* __restrict__ Bl,
    const float* __restrict__ bias, float* __restrict__ C,
    __nv_bfloat16* __restrict__ Ch, __nv_bfloat16* __restrict__ Cl,
    int M, int N, int K, float alpha,
    long zsA, long zsB, long zsC, int zsBias)
{
    extern __shared__ __align__(16) __nv_bfloat16 sm[];
    const long z = blockIdx.z;
    Ah += z * zsA; Al += z * zsA;
    Bh += z * zsB; Bl += z * zsB;
    const float* bz = bias ? bias + (long)z * zsBias : nullptr;

    const int tid = threadIdx.x, warp = tid >> 5, lane = tid & 31;
    const int g = lane >> 2, t = lane & 3, wm = warp >> 2, wn = warp & 3;
    const int lrow = lane & 15, lkof = (lane & 16) >> 1;
    const int rowC = blockIdx.y * 128, colC = blockIdx.x * 128;

    const __nv_bfloat16* srcs[4] = { Ah + (long)rowC * K, Al + (long)rowC * K,
                                     Bh + (long)colC * K, Bl + (long)colC * K };

    float acc[4][4][4];
    #pragma unroll
    for (int mi = 0; mi < 4; mi++)
        #pragma unroll
        for (int ni = 0; ni < 4; ni++)
            #pragma unroll
            for (int r = 0; r < 4; r++) acc[mi][ni][r] = 0.f;

    const int rr0 = tid >> 2,            ss0 = tid & 3;
    const int rr1 = (tid + 256) >> 2,    ss1 = (tid + 256) & 3;

    auto load_stage = [&](int stg, int k0) {
        __nv_bfloat16* base = sm + stg * 4 * (128 * SPAD);
        #pragma unroll
        for (int m = 0; m < 4; m++) {
            __nv_bfloat16* d = base + m * (128 * SPAD);
            cpa16(d + rr0 * SPAD + ss0 * 8, srcs[m] + (long)rr0 * K + k0 + ss0 * 8);
            cpa16(d + rr1 * SPAD + ss1 * 8, srcs[m] + (long)rr1 * K + k0 + ss1 * 8);
        }
    };

    auto compute = [&](int stg) {
        const __nv_bfloat16* bAh = sm + (stg * 4 + 0) * (128 * SPAD);
        const __nv_bfloat16* bAl = sm + (stg * 4 + 1) * (128 * SPAD);
        const __nv_bfloat16* bBh = sm + (stg * 4 + 2) * (128 * SPAD);
        const __nv_bfloat16* bBl = sm + (stg * 4 + 3) * (128 * SPAD);
        #pragma unroll
        for (int ks = 0; ks < 2; ks++) {
            const int kb = ks * 16 + lkof;
            uint32_t bh[4][2], bl[4][2];
            #pragma unroll
            for (int p = 0; p < 2; p++) {
                int n = wn * 32 + p * 16 + lrow;
                uint32_t r0, r1, r2, r3;
                ldmx4(r0, r1, r2, r3, smem_u32(bBh + n * SPAD + kb));
                bh[2*p][0] = r0; bh[2*p+1][0] = r1; bh[2*p][1] = r2; bh[2*p+1][1] = r3;
                ldmx4(r0, r1, r2, r3, smem_u32(bBl + n * SPAD + kb));
                bl[2*p][0] = r0; bl[2*p+1][0] = r1; bl[2*p][1] = r2; bl[2*p+1][1] = r3;
            }
            #pragma unroll
            for (int mi = 0; mi < 4; mi++) {
                int mrow = wm * 64 + mi * 16 + lrow;
                uint32_t ah[4], al[4];
                ldmx4(ah[0], ah[1], ah[2], ah[3], smem_u32(bAh + mrow * SPAD + kb));
                ldmx4(al[0], al[1], al[2], al[3], smem_u32(bAl + mrow * SPAD + kb));
                #pragma unroll
                for (int ni = 0; ni < 4; ni++) {
                    mma16(acc[mi][ni], ah, bh[ni]);
                    mma16(acc[mi][ni], ah, bl[ni]);
                    mma16(acc[mi][ni], al, bh[ni]);
                }
            }
        }
    };

    const int KT = K >> 5;
    load_stage(0, 0); cp_commit();
    for (int kt = 0; kt < KT; kt++) {
        if (kt + 1 < KT) { load_stage((kt + 1) & 1, (kt + 1) * 32); cp_commit(); cp_wait<1>(); }
        else             { cp_wait<0>(); }
        __syncthreads();
        compute(kt & 1);
        __syncthreads();
    }

    float*         Cz  = (EPI == 0) ? C  + z * zsC : nullptr;
    __nv_bfloat16* Chz = (EPI == 1) ? Ch + z * zsC : nullptr;
    __nv_bfloat16* Clz = (EPI == 1) ? Cl + z * zsC : nullptr;

    #pragma unroll
    for (int mi = 0; mi < 4; mi++) {
        #pragma unroll
        for (int ni = 0; ni < 4; ni++) {
            int r0 = rowC + wm * 64 + mi * 16 + g;
            int cc = colC + wn * 32 + ni * 8 + 2 * t;
            float b0 = bz ? bz[cc] : 0.f, b1 = bz ? bz[cc + 1] : 0.f;
            float c00 = fmaf(acc[mi][ni][0], alpha, b0);
            float c01 = fmaf(acc[mi][ni][1], alpha, b1);
            float c10 = fmaf(acc[mi][ni][2], alpha, b0);
            float c11 = fmaf(acc[mi][ni][3], alpha, b1);
            if (EPI == 0) {
                float2 o0 = {c00, c01}, o1 = {c10, c11};
                *(float2*)(Cz + (long)r0 * N + cc)       = o0;
                *(float2*)(Cz + (long)(r0 + 8) * N + cc) = o1;
            } else {
                store_split2(Chz + (long)r0 * N + cc,       Clz + (long)r0 * N + cc,       c00, c01);
                store_split2(Chz + (long)(r0 + 8) * N + cc, Clz + (long)(r0 + 8) * N + cc, c10, c11);
            }
        }
    }
}

// ---------------------------------------------------------------------------
// gemm_pv: O = P @ V per (b,h). 1-pass bf16. P [2048,2048] (cp.async),
// V [2048,64] (transpose-filled). Block 128x64, BK=32, warp 64x16.
// Epilogue: split bf16 (Oh,Ol).
// ---------------------------------------------------------------------------
__global__ __launch_bounds__(256) void gemm_pv(
    const __nv_bfloat16* __restrict__ P, const __nv_bfloat16* __restrict__ V,
    __nv_bfloat16* __restrict__ Oh, __nv_bfloat16* __restrict__ Ol)
{
    __shared__ __align__(16) __nv_bfloat16 sP[2][128 * SPAD];
    __shared__ __align__(16) __nv_bfloat16 sV[2][64 * SPAD];   // [n][k]

    const long z = blockIdx.z;
    const __nv_bfloat16* Pp = P + z * ATTN_STRIDE + (long)blockIdx.y * 128 * 2048;
    const __nv_bfloat16* Vp = V + z * HEAD_STRIDE;
    __nv_bfloat16* Ohz = Oh + z * HEAD_STRIDE + (long)blockIdx.y * 128 * 64;
    __nv_bfloat16* Olz = Ol + z * HEAD_STRIDE + (long)blockIdx.y * 128 * 64;

    const int tid = threadIdx.x, warp = tid >> 5, lane = tid & 31;
    const int g = lane >> 2, t = lane & 3, wm = warp >> 2, wn = warp & 3;
    const int lrow = lane & 15, lkof = (lane & 16) >> 1;

    float acc[4][2][4];
    #pragma unroll
    for (int mi = 0; mi < 4; mi++)
        #pragma unroll
        for (int ni = 0; ni < 2; ni++)
            #pragma unroll
            for (int r = 0; r < 4; r++) acc[mi][ni][r] = 0.f;

    const int rr0 = tid >> 2,         ss0 = tid & 3;
    const int rr1 = (tid + 256) >> 2, ss1 = (tid + 256) & 3;
    const int vr = tid >> 3, vs = tid & 7;     // V: row k (32), 16B segment (8)

    auto loadP = [&](int stg, int k0) {
        cpa16(&sP[stg][rr0 * SPAD + ss0 * 8], Pp + (long)rr0 * 2048 + k0 + ss0 * 8);
        cpa16(&sP[stg][rr1 * SPAD + ss1 * 8], Pp + (long)rr1 * 2048 + k0 + ss1 * 8);
    };
    auto loadVreg = [&](int k0) -> uint4 {
        return *(const uint4*)(Vp + (long)(k0 + vr) * 64 + vs * 8);
    };
    auto stsV = [&](int stg, uint4 vv) {
        __nv_bfloat16 e[8];
        *(uint4*)e = vv;
        #pragma unroll
        for (int j = 0; j < 8; j++) sV[stg][(vs * 8 + j) * SPAD + vr] = e[j];
    };

    auto compute = [&](int stg) {
        #pragma unroll
        for (int ks = 0; ks < 2; ks++) {
            const int kb = ks * 16 + lkof;
            uint32_t bh[2][2];
            {
                int n = wn * 16 + lrow;
                uint32_t r0, r1, r2, r3;
                ldmx4(r0, r1, r2, r3, smem_u32(&sV[stg][n * SPAD + kb]));
                bh[0][0] = r0; bh[1][0] = r1; bh[0][1] = r2; bh[1][1] = r3;
            }
            #pragma unroll
            for (int mi = 0; mi < 4; mi++) {
                int mrow = wm * 64 + mi * 16 + lrow;
                uint32_t ah[4];
                ldmx4(ah[0], ah[1], ah[2], ah[3], smem_u32(&sP[stg][mrow * SPAD + kb]));
                mma16(acc[mi][0], ah, bh[0]);
                mma16(acc[mi][1], ah, bh[1]);
            }
        }
    };

    loadP(0, 0); cp_commit();
    stsV(0, loadVreg(0));
    for (int kt = 0; kt < 64; kt++) {
        uint4 vv;
        const bool pre = (kt + 1 < 64);
        if (pre) { loadP((kt + 1) & 1, (kt + 1) * 32); cp_commit(); vv = loadVreg((kt + 1) * 32); }
        if (pre) cp_wait<1>(); else cp_wait<0>();
        __syncthreads();
        compute(kt & 1);
        if (pre) stsV((kt + 1) & 1, vv);
        __syncthreads();
    }

    #pragma unroll
    for (int mi = 0; mi < 4; mi++) {
        #pragma unroll
        for (int ni = 0; ni < 2; ni++) {
            int r0 = wm * 64 + mi * 16 + g;
            int cc = wn * 16 + ni * 8 + 2 * t;
            store_split2(Ohz + (long)r0 * 64 + cc,       Olz + (long)r0 * 64 + cc,
                         acc[mi][ni][0], acc[mi][ni][1]);
            store_split2(Ohz + (long)(r0 + 8) * 64 + cc, Olz + (long)(r0 + 8) * 64 + cc,
                         acc[mi][ni][2], acc[mi][ni][3]);
        }
    }
}

// ---------------------------------------------------------------------------
// Row softmax, in place; also emits bf16 copy for the PV GEMM.
// ---------------------------------------------------------------------------
__global__ __launch_bounds__(256) void softmax_rows(float* __restrict__ attn,
                                                    __nv_bfloat16* __restrict__ pb)
{
    float*         p = attn + (long)blockIdx.x * 2048;
    __nv_bfloat16* q = pb   + (long)blockIdx.x * 2048;
    const int tid = threadIdx.x;
    const int warp = tid >> 5, lane = tid & 31;

    float v[8];
    #pragma unroll
    for (int i = 0; i < 8; i++) v[i] = p[tid + i * 256];

    float m = v[0];
    #pragma unroll
    for (int i = 1; i < 8; i++) m = fmaxf(m, v[i]);
    #pragma unroll
    for (int off = 16; off; off >>= 1)
        m = fmaxf(m, __shfl_xor_sync(0xffffffffu, m, off));

    __shared__ float red[8];
    if (lane == 0) red[warp] = m;
    __syncthreads();
    float mm = red[0];
    #pragma unroll
    for (int w = 1; w < 8; w++) mm = fmaxf(mm, red[w]);

    float s = 0.f;
    #pragma unroll
    for (int i = 0; i < 8; i++) { v[i] = expf(v[i] - mm); s += v[i]; }
    #pragma unroll
    for (int off = 16; off; off >>= 1)
        s += __shfl_xor_sync(0xffffffffu, s, off);

    __syncthreads();
    if (lane == 0) red[warp] = s;
    __syncthreads();
    float tot = 0.f;
    #pragma unroll
    for (int w = 0; w < 8; w++) tot += red[w];
    float inv = 1.f / tot;

    #pragma unroll
    for (int i = 0; i < 8; i++) {
        float r = v[i] * inv;
        p[tid + i * 256] = r;
        q[tid + i * 256] = __float2bfloat16(r);
    }
}

// ---------------------------------------------------------------------------
extern "C" void kernel_launch(void* const* d_in, const int* in_sizes, int n_in,
                              void* d_out, int out_size)
{
    const float* pre_q = (const float*)d_in[0];
    const float* pre_k = (const float*)d_in[1];
    const float* pre_v = (const float*)d_in[2];
    const float* Wq = (const float*)d_in[3];
    const float* bq = (const float*)d_in[4];
    const float* Wk = (const float*)d_in[5];
    const float* bk = (const float*)d_in[6];
    const float* Wv = (const float*)d_in[7];
    const float* bv = (const float*)d_in[8];
    const float* Wo = (const float*)d_in[9];
    const float* bo = (const float*)d_in[10];

    float* proj = (float*)d_out;
    float* attn = proj + PROJ_ELEMS;

    __nv_bfloat16 *preh, *prel, *Wh, *Wl, *Woh, *Wol, *QKVh, *QKVl, *Pb, *Oh, *Ol;
    float* bias3;
    cudaGetSymbolAddress((void**)&preh, g_preh);
    cudaGetSymbolAddress((void**)&prel, g_prel);
    cudaGetSymbolAddress((void**)&Wh, g_Wh);
    cudaGetSymbolAddress((void**)&Wl, g_Wl);
    cudaGetSymbolAddress((void**)&Woh, g_Woh);
    cudaGetSymbolAddress((void**)&Wol, g_Wol);
    cudaGetSymbolAddress((void**)&bias3, g_bias3);
    cudaGetSymbolAddress((void**)&QKVh, g_QKVh);
    cudaGetSymbolAddress((void**)&QKVl, g_QKVl);
    cudaGetSymbolAddress((void**)&Pb, g_Pb);
    cudaGetSymbolAddress((void**)&Oh, g_Oh);
    cudaGetSymbolAddress((void**)&Ol, g_Ol);

    static bool attr_done = false;
    if (!attr_done) {
        cudaFuncSetAttribute(gemm3<0>, cudaFuncAttributeMaxDynamicSharedMemorySize, 81920);
        cudaFuncSetAttribute(gemm3<1>, cudaFuncAttributeMaxDynamicSharedMemorySize, 81920);
        attr_done = true;
    }

    // ---- prep: split inputs/weights to bf16 hi/lo; gather biases ----
    splitk<<<4096, 256>>>((const float4*)pre_q, preh,             prel,             1048576);
    splitk<<<4096, 256>>>((const float4*)pre_k, preh + 4194304,   prel + 4194304,   1048576);
    splitk<<<4096, 256>>>((const float4*)pre_v, preh + 8388608,   prel + 8388608,   1048576);
    splitk<<<1024, 256>>>((const float4*)Wq,    Wh,               Wl,               262144);
    splitk<<<1024, 256>>>((const float4*)Wk,    Wh + 1048576,     Wl + 1048576,     262144);
    splitk<<<1024, 256>>>((const float4*)Wv,    Wh + 2097152,     Wl + 2097152,     262144);
    splitk<<<1024, 256>>>((const float4*)Wo,    Woh,              Wol,              262144);
    biascopy<<<4, 256>>>(bq, bk, bv, bias3);

    // ---- QKV projections (merged z=3): split bf16 outputs ----
    gemm3<1><<<dim3(8, 32, 3), 256, 81920>>>(
        preh, prel, Wh, Wl, bias3, nullptr, QKVh, QKVl,
        4096, 1024, 1024, 1.f, 4194304, 1048576, 4194304, 1024);

    // ---- scores per head: Q @ K^T * 1/8 -> attn (fp32) ----
    gemm3<0><<<dim3(16, 16, 32), 256, 81920>>>(
        QKVh, QKVl, QKVh + 4194304, QKVl + 4194304, nullptr, attn, nullptr, nullptr,
        2048, 2048, 64, 0.125f, HEAD_STRIDE, HEAD_STRIDE, ATTN_STRIDE, 0);

    // ---- softmax (in-place) + bf16 emit ----
    softmax_rows<<<65536, 256>>>(attn, Pb);

    // ---- O = attn @ V (1-pass bf16), split outputs ----
    gemm_pv<<<dim3(1, 16, 32), 256>>>(Pb, QKVh + 8388608, Oh, Ol);

    // ---- output projection: proj = O @ Wo^T + bo ----
    gemm3<0><<<dim3(8, 32, 1), 256, 81920>>>(
        Oh, Ol, Woh, Wol, bo, proj, nullptr, nullptr,
        4096, 1024, 1024, 1.f, 0, 0, 0, 0);
}

// round 8
// speedup vs baseline: 1.4152x; 1.4152x over previous
#include <cuda_runtime.h>
#include <cuda_bf16.h>
#include <cstdint>

// Shapes (fixed): B=2, S=2048, D=1024, H=16, d=64
// head h of batch b = contiguous block (b*2048 + h*128)*1024 viewed as [2048,64] row-major
// d_out = [ proj : 4194304 f32 ][ attn : 134217728 f32 ]

#define PROJ_ELEMS 4194304LL
#define HEAD_STRIDE 131072LL
#define ATTN_STRIDE 4194304LL

// ---------------- persistent bf16 split buffers (device globals) ----------------
__device__ __nv_bfloat16 g_preh[12582912], g_prel[12582912];   // pre_q|pre_k|pre_v
__device__ __nv_bfloat16 g_Wh[3145728],   g_Wl[3145728];       // Wq|Wk|Wv
__device__ __nv_bfloat16 g_Woh[1048576],  g_Wol[1048576];
__device__ float         g_bias3[3072];                        // bq|bk|bv
__device__ __nv_bfloat16 g_QKVh[12582912], g_QKVl[12582912];   // Q|K|V (hi/lo)
__device__ __nv_bfloat16 g_Vth[4194304],  g_Vtl[4194304];      // V transposed [head][64][2048]
__device__ __nv_bfloat16 g_Oh[4194304],   g_Ol[4194304];

// ---------------- helpers ----------------
__device__ __forceinline__ uint32_t smem_u32(const void* p) {
    return (uint32_t)__cvta_generic_to_shared(p);
}
__device__ __forceinline__ void cpa16(__nv_bfloat16* s, const __nv_bfloat16* g) {
    asm volatile("cp.async.cg.shared.global [%0], [%1], 16;"
                 :: "r"(smem_u32(s)), "l"(__cvta_generic_to_global(g)));
}
__device__ __forceinline__ void cp_commit() { asm volatile("cp.async.commit_group;"); }
template<int NW> __device__ __forceinline__ void cp_wait() {
    asm volatile("cp.async.wait_group %0;" :: "n"(NW));
}
__device__ __forceinline__ void ldmx4(uint32_t& r0, uint32_t& r1, uint32_t& r2, uint32_t& r3,
                                      uint32_t addr) {
    asm volatile("ldmatrix.sync.aligned.m8n8.x4.shared.b16 {%0,%1,%2,%3}, [%4];"
                 : "=r"(r0), "=r"(r1), "=r"(r2), "=r"(r3) : "r"(addr));
}
__device__ __forceinline__ void mma16(float* c, const uint32_t* a, const uint32_t* b) {
    asm volatile(
        "mma.sync.aligned.m16n8k16.row.col.f32.bf16.bf16.f32 "
        "{%0,%1,%2,%3},{%4,%5,%6,%7},{%8,%9},{%0,%1,%2,%3};"
        : "+f"(c[0]), "+f"(c[1]), "+f"(c[2]), "+f"(c[3])
        : "r"(a[0]), "r"(a[1]), "r"(a[2]), "r"(a[3]), "r"(b[0]), "r"(b[1]));
}
__device__ __forceinline__ void store_split2(__nv_bfloat16* h, __nv_bfloat16* l,
                                             float a, float b) {
    __nv_bfloat16 ha = __float2bfloat16(a), hb = __float2bfloat16(b);
    __nv_bfloat16 la = __float2bfloat16(a - __bfloat162float(ha));
    __nv_bfloat16 lb = __float2bfloat16(b - __bfloat162float(hb));
    __nv_bfloat162 hp; hp.x = ha; hp.y = hb;
    __nv_bfloat162 lp; lp.x = la; lp.y = lb;
    *(__nv_bfloat162*)h = hp;
    *(__nv_bfloat162*)l = lp;
}

#define SPAD 40   // smem row stride in bf16 (32 data + 8 pad) -> conflict-free ldmatrix

// ---------------------------------------------------------------------------
// prep kernels
// ---------------------------------------------------------------------------
__global__ void splitk(const float4* __restrict__ x,
                       __nv_bfloat16* __restrict__ h, __nv_bfloat16* __restrict__ l, int n4)
{
    int i = blockIdx.x * blockDim.x + threadIdx.x;
    if (i >= n4) return;
    float4 v = x[i];
    float vs[4] = {v.x, v.y, v.z, v.w};
    __nv_bfloat16 hh[4], ll[4];
    #pragma unroll
    for (int c = 0; c < 4; c++) {
        hh[c] = __float2bfloat16(vs[c]);
        ll[c] = __float2bfloat16(vs[c] - __bfloat162float(hh[c]));
    }
    __nv_bfloat162 h0; h0.x = hh[0]; h0.y = hh[1];
    __nv_bfloat162 h1; h1.x = hh[2]; h1.y = hh[3];
    __nv_bfloat162 l0; l0.x = ll[0]; l0.y = ll[1];
    __nv_bfloat162 l1; l1.x = ll[2]; l1.y = ll[3];
    *(__nv_bfloat162*)(h + 4 * i)     = h0;
    *(__nv_bfloat162*)(h + 4 * i + 2) = h1;
    *(__nv_bfloat162*)(l + 4 * i)     = l0;
    *(__nv_bfloat162*)(l + 4 * i + 2) = l1;
}

__global__ void biascopy(const float* __restrict__ bq, const float* __restrict__ bk,
                         const float* __restrict__ bv, float* __restrict__ dst)
{
    int i = blockIdx.x * blockDim.x + threadIdx.x;
    if (i < 1024) { dst[i] = bq[i]; dst[1024 + i] = bk[i]; dst[2048 + i] = bv[i]; }
}

// Transpose V per head: in [2048,64] -> out [64,2048] (both hi and lo).
// grid (32 k-tiles, 32 heads), 256 threads, 64x64 tiles.
__global__ __launch_bounds__(256) void transposeV(
    const __nv_bfloat16* __restrict__ Vh, const __nv_bfloat16* __restrict__ Vl,
    __nv_bfloat16* __restrict__ Vth, __nv_bfloat16* __restrict__ Vtl)
{
    __shared__ __nv_bfloat16 th[64][72], tl[64][72];
    const long head = blockIdx.y;
    const int  k0   = blockIdx.x * 64;
    const __nv_bfloat16* inh = Vh + head * HEAD_STRIDE + (long)k0 * 64;
    const __nv_bfloat16* inl = Vl + head * HEAD_STRIDE + (long)k0 * 64;
    __nv_bfloat16* outh = Vth + head * HEAD_STRIDE + k0;
    __nv_bfloat16* outl = Vtl + head * HEAD_STRIDE + k0;

    const int tid = threadIdx.x;
    const int lr = tid >> 2, seg = tid & 3;          // row 0..63, seg 0..3 (16 cols each)
    #pragma unroll
    for (int i = 0; i < 2; i++) {
        int col = seg * 16 + i * 8;
        uint4 vh = *(const uint4*)(inh + (long)lr * 64 + col);
        uint4 vl = *(const uint4*)(inl + (long)lr * 64 + col);
        *(uint4*)&th[lr][col] = vh;
        *(uint4*)&tl[lr][col] = vl;
    }
    __syncthreads();
    #pragma unroll
    for (int i = 0; i < 2; i++) {
        int kk = seg * 16 + i * 8;                   // k within tile
        __nv_bfloat16 eh[8], el[8];
        #pragma unroll
        for (int j = 0; j < 8; j++) { eh[j] = th[kk + j][lr]; el[j] = tl[kk + j][lr]; }
        *(uint4*)(outh + (long)lr * 2048 + kk) = *(uint4*)eh;
        *(uint4*)(outl + (long)lr * 2048 + kk) = *(uint4*)el;
    }
}

// ---------------------------------------------------------------------------
// gemm3: 3-pass split-bf16 NT GEMM, cp.async 2-stage pipelined.
//   C[m,n] = alpha * sum_k (Ah+Al)[m,k]*(Bh+Bl)[n,k] (+bias[n])   [lo*lo dropped]
//   EPI=0: fp32 C (+bias).  EPI=1: split bf16 (Ch,Cl) (+bias).
// Block 128x128, BK=32, 256 threads, warp tile 64x32. dyn smem 81920B.
// ---------------------------------------------------------------------------
template<int EPI>
__global__ __launch_bounds__(256) void gemm3(
    const __nv_bfloat16* __restrict__ Ah, const __nv_bfloat16* __restrict__ Al,
    const __nv_bfloat16* __restrict__ Bh, const __nv_bfloat16* __restrict__ Bl,
    const float* __restrict__ bias, float* __restrict__ C,
    __nv_bfloat16* __restrict__ Ch, __nv_bfloat16* __restrict__ Cl,
    int M, int N, int K, float alpha,
    long zsA, long zsB, long zsC, int zsBias)
{
    extern __shared__ __align__(16) __nv_bfloat16 sm[];
    const long z = blockIdx.z;
    Ah += z * zsA; Al += z * zsA;
    Bh += z * zsB; Bl += z * zsB;
    const float* bz = bias ? bias + (long)z * zsBias : nullptr;

    const int tid = threadIdx.x, warp = tid >> 5, lane = tid & 31;
    const int g = lane >> 2, t = lane & 3, wm = warp >> 2, wn = warp & 3;
    const int lrow = lane & 15, lkof = (lane & 16) >> 1;
    const int rowC = blockIdx.y * 128, colC = blockIdx.x * 128;

    const __nv_bfloat16* srcs[4] = { Ah + (long)rowC * K, Al + (long)rowC * K,
                                     Bh + (long)colC * K, Bl + (long)colC * K };

    float acc[4][4][4];
    #pragma unroll
    for (int mi = 0; mi < 4; mi++)
        #pragma unroll
        for (int ni = 0; ni < 4; ni++)
            #pragma unroll
            for (int r = 0; r < 4; r++) acc[mi][ni][r] = 0.f;

    const int rr0 = tid >> 2,            ss0 = tid & 3;
    const int rr1 = (tid + 256) >> 2,    ss1 = (tid + 256) & 3;

    auto load_stage = [&](int stg, int k0) {
        __nv_bfloat16* base = sm + stg * 4 * (128 * SPAD);
        #pragma unroll
        for (int m = 0; m < 4; m++) {
            __nv_bfloat16* d = base + m * (128 * SPAD);
            cpa16(d + rr0 * SPAD + ss0 * 8, srcs[m] + (long)rr0 * K + k0 + ss0 * 8);
            cpa16(d + rr1 * SPAD + ss1 * 8, srcs[m] + (long)rr1 * K + k0 + ss1 * 8);
        }
    };

    auto compute = [&](int stg) {
        const __nv_bfloat16* bAh = sm + (stg * 4 + 0) * (128 * SPAD);
        const __nv_bfloat16* bAl = sm + (stg * 4 + 1) * (128 * SPAD);
        const __nv_bfloat16* bBh = sm + (stg * 4 + 2) * (128 * SPAD);
        const __nv_bfloat16* bBl = sm + (stg * 4 + 3) * (128 * SPAD);
        #pragma unroll
        for (int ks = 0; ks < 2; ks++) {
            const int kb = ks * 16 + lkof;
            uint32_t bh[4][2], bl[4][2];
            #pragma unroll
            for (int p = 0; p < 2; p++) {
                int n = wn * 32 + p * 16 + lrow;
                uint32_t r0, r1, r2, r3;
                ldmx4(r0, r1, r2, r3, smem_u32(bBh + n * SPAD + kb));
                bh[2*p][0] = r0; bh[2*p+1][0] = r1; bh[2*p][1] = r2; bh[2*p+1][1] = r3;
                ldmx4(r0, r1, r2, r3, smem_u32(bBl + n * SPAD + kb));
                bl[2*p][0] = r0; bl[2*p+1][0] = r1; bl[2*p][1] = r2; bl[2*p+1][1] = r3;
            }
            #pragma unroll
            for (int mi = 0; mi < 4; mi++) {
                int mrow = wm * 64 + mi * 16 + lrow;
                uint32_t ah[4], al[4];
                ldmx4(ah[0], ah[1], ah[2], ah[3], smem_u32(bAh + mrow * SPAD + kb));
                ldmx4(al[0], al[1], al[2], al[3], smem_u32(bAl + mrow * SPAD + kb));
                #pragma unroll
                for (int ni = 0; ni < 4; ni++) {
                    mma16(acc[mi][ni], ah, bh[ni]);
                    mma16(acc[mi][ni], ah, bl[ni]);
                    mma16(acc[mi][ni], al, bh[ni]);
                }
            }
        }
    };

    const int KT = K >> 5;
    load_stage(0, 0); cp_commit();
    for (int kt = 0; kt < KT; kt++) {
        if (kt + 1 < KT) { load_stage((kt + 1) & 1, (kt + 1) * 32); cp_commit(); cp_wait<1>(); }
        else             { cp_wait<0>(); }
        __syncthreads();
        compute(kt & 1);
        __syncthreads();
    }

    float*         Cz  = (EPI == 0) ? C  + z * zsC : nullptr;
    __nv_bfloat16* Chz = (EPI == 1) ? Ch + z * zsC : nullptr;
    __nv_bfloat16* Clz = (EPI == 1) ? Cl + z * zsC : nullptr;

    #pragma unroll
    for (int mi = 0; mi < 4; mi++) {
        #pragma unroll
        for (int ni = 0; ni < 4; ni++) {
            int r0 = rowC + wm * 64 + mi * 16 + g;
            int cc = colC + wn * 32 + ni * 8 + 2 * t;
            float b0 = bz ? bz[cc] : 0.f, b1 = bz ? bz[cc + 1] : 0.f;
            float c00 = fmaf(acc[mi][ni][0], alpha, b0);
            float c01 = fmaf(acc[mi][ni][1], alpha, b1);
            float c10 = fmaf(acc[mi][ni][2], alpha, b0);
            float c11 = fmaf(acc[mi][ni][3], alpha, b1);
            if (EPI == 0) {
                float2 o0 = {c00, c01}, o1 = {c10, c11};
                *(float2*)(Cz + (long)r0 * N + cc)       = o0;
                *(float2*)(Cz + (long)(r0 + 8) * N + cc) = o1;
            } else {
                store_split2(Chz + (long)r0 * N + cc,       Clz + (long)r0 * N + cc,       c00, c01);
                store_split2(Chz + (long)(r0 + 8) * N + cc, Clz + (long)(r0 + 8) * N + cc, c10, c11);
            }
        }
    }
}

// ---------------------------------------------------------------------------
// gemm_pv3: O = P @ V per (b,h), 3-pass split. P fp32 (LDG + in-kernel split),
// V from pre-transposed split bf16 Vt [64,2048] (cp.async).
// Block 128x64, BK=32, 256 thr, warp tile 64x16. Epilogue: split Oh/Ol.
// dyn smem: sPh/sPl 2st*128*40 + sVh/sVl 2st*64*40 = 61440B.
// ---------------------------------------------------------------------------
__global__ __launch_bounds__(256) void gemm_pv3(
    const float* __restrict__ P,
    const __nv_bfloat16* __restrict__ Vth, const __nv_bfloat16* __restrict__ Vtl,
    __nv_bfloat16* __restrict__ Oh, __nv_bfloat16* __restrict__ Ol)
{
    extern __shared__ __align__(16) __nv_bfloat16 sm[];
    __nv_bfloat16* sPh = sm;                       // [2][128*SPAD]
    __nv_bfloat16* sPl = sm + 2 * 128 * SPAD;
    __nv_bfloat16* sVh = sm + 4 * 128 * SPAD;      // [2][64*SPAD]
    __nv_bfloat16* sVl = sm + 4 * 128 * SPAD + 2 * 64 * SPAD;

    const long z = blockIdx.z;
    const float* Pp = P + z * ATTN_STRIDE + (long)blockIdx.y * 128 * 2048;
    const __nv_bfloat16* Vh = Vth + z * HEAD_STRIDE;
    const __nv_bfloat16* Vl = Vtl + z * HEAD_STRIDE;
    __nv_bfloat16* Ohz = Oh + z * HEAD_STRIDE + (long)blockIdx.y * 128 * 64;
    __nv_bfloat16* Olz = Ol + z * HEAD_STRIDE + (long)blockIdx.y * 128 * 64;

    const int tid = threadIdx.x, warp = tid >> 5, lane = tid & 31;
    const int g = lane >> 2, t = lane & 3, wm = warp >> 2, wn = warp & 3;
    const int lrow = lane & 15, lkof = (lane & 16) >> 1;

    float acc[4][2][4];
    #pragma unroll
    for (int mi = 0; mi < 4; mi++)
        #pragma unroll
        for (int ni = 0; ni < 2; ni++)
            #pragma unroll
            for (int r = 0; r < 4; r++) acc[mi][ni][r] = 0.f;

    // P: 128x32 fp32 per tile -> 4 float4 per thread
    const int pr = tid >> 3, ps = tid & 7;          // covers rows 0..31 per i-step
    // V: 64x32 bf16 per array -> 1 cp.async per thread per array
    const int nr = tid >> 2, ns = tid & 3;

    float4 pregs[4];
    auto ldP = [&](int k0) {
        #pragma unroll
        for (int i = 0; i < 4; i++) {
            int lr = pr + i * 32;
            pregs[i] = *(const float4*)(Pp + (long)lr * 2048 + k0 + ps * 4);
        }
    };
    auto stsP = [&](int stg) {
        __nv_bfloat16* dh = sPh + stg * 128 * SPAD;
        __nv_bfloat16* dl = sPl + stg * 128 * SPAD;
        #pragma unroll
        for (int i = 0; i < 4; i++) {
            int lr = pr + i * 32;
            float vals[4] = {pregs[i].x, pregs[i].y, pregs[i].z, pregs[i].w};
            #pragma unroll
            for (int c = 0; c < 4; c++) {
                __nv_bfloat16 h = __float2bfloat16(vals[c]);
                __nv_bfloat16 l = __float2bfloat16(vals[c] - __bfloat162float(h));
                dh[lr * SPAD + ps * 4 + c] = h;
                dl[lr * SPAD + ps * 4 + c] = l;
            }
        }
    };
    auto loadV = [&](int stg, int k0) {
        cpa16(sVh + stg * 64 * SPAD + nr * SPAD + ns * 8, Vh + (long)nr * 2048 + k0 + ns * 8);
        cpa16(sVl + stg * 64 * SPAD + nr * SPAD + ns * 8, Vl + (long)nr * 2048 + k0 + ns * 8);
    };

    auto compute = [&](int stg) {
        const __nv_bfloat16* bPh = sPh + stg * 128 * SPAD;
        const __nv_bfloat16* bPl = sPl + stg * 128 * SPAD;
        const __nv_bfloat16* bVh = sVh + stg * 64 * SPAD;
        const __nv_bfloat16* bVl = sVl + stg * 64 * SPAD;
        #pragma unroll
        for (int ks = 0; ks < 2; ks++) {
            const int kb = ks * 16 + lkof;
            uint32_t bh[2][2], bl[2][2];
            {
                int n = wn * 16 + lrow;
                uint32_t r0, r1, r2, r3;
                ldmx4(r0, r1, r2, r3, smem_u32(bVh + n * SPAD + kb));
                bh[0][0] = r0; bh[1][0] = r1; bh[0][1] = r2; bh[1][1] = r3;
                ldmx4(r0, r1, r2, r3, smem_u32(bVl + n * SPAD + kb));
                bl[0][0] = r0; bl[1][0] = r1; bl[0][1] = r2; bl[1][1] = r3;
            }
            #pragma unroll
            for (int mi = 0; mi < 4; mi++) {
                int mrow = wm * 64 + mi * 16 + lrow;
                uint32_t ah[4], al[4];
                ldmx4(ah[0], ah[1], ah[2], ah[3], smem_u32(bPh + mrow * SPAD + kb));
                ldmx4(al[0], al[1], al[2], al[3], smem_u32(bPl + mrow * SPAD + kb));
                #pragma unroll
                for (int ni = 0; ni < 2; ni++) {
                    mma16(acc[mi][ni], ah, bh[ni]);
                    mma16(acc[mi][ni], ah, bl[ni]);
                    mma16(acc[mi][ni], al, bh[ni]);
                }
            }
        }
    };

    ldP(0);
    loadV(0, 0); cp_commit();
    for (int kt = 0; kt < 64; kt++) {
        stsP(kt & 1);
        cp_wait<0>();
        __syncthreads();
        if (kt + 1 < 64) {
            ldP((kt + 1) * 32);
            loadV((kt + 1) & 1, (kt + 1) * 32); cp_commit();
        }
        compute(kt & 1);
        __syncthreads();
    }

    #pragma unroll
    for (int mi = 0; mi < 4; mi++) {
        #pragma unroll
        for (int ni = 0; ni < 2; ni++) {
            int r0 = wm * 64 + mi * 16 + g;
            int cc = wn * 16 + ni * 8 + 2 * t;
            store_split2(Ohz + (long)r0 * 64 + cc,       Olz + (long)r0 * 64 + cc,
                         acc[mi][ni][0], acc[mi][ni][1]);
            store_split2(Ohz + (long)(r0 + 8) * 64 + cc, Olz + (long)(r0 + 8) * 64 + cc,
                         acc[mi][ni][2], acc[mi][ni][3]);
        }
    }
}

// ---------------------------------------------------------------------------
// Row softmax, in place (fp32 only).
// ---------------------------------------------------------------------------
__global__ __launch_bounds__(256) void softmax_rows(float* __restrict__ attn)
{
    float* p = attn + (long)blockIdx.x * 2048;
    const int tid = threadIdx.x;
    const int warp = tid >> 5, lane = tid & 31;

    float v[8];
    #pragma unroll
    for (int i = 0; i < 8; i++) v[i] = p[tid + i * 256];

    float m = v[0];
    #pragma unroll
    for (int i = 1; i < 8; i++) m = fmaxf(m, v[i]);
    #pragma unroll
    for (int off = 16; off; off >>= 1)
        m = fmaxf(m, __shfl_xor_sync(0xffffffffu, m, off));

    __shared__ float red[8];
    if (lane == 0) red[warp] = m;
    __syncthreads();
    float mm = red[0];
    #pragma unroll
    for (int w = 1; w < 8; w++) mm = fmaxf(mm, red[w]);

    float s = 0.f;
    #pragma unroll
    for (int i = 0; i < 8; i++) { v[i] = expf(v[i] - mm); s += v[i]; }
    #pragma unroll
    for (int off = 16; off; off >>= 1)
        s += __shfl_xor_sync(0xffffffffu, s, off);

    __syncthreads();
    if (lane == 0) red[warp] = s;
    __syncthreads();
    float tot = 0.f;
    #pragma unroll
    for (int w = 0; w < 8; w++) tot += red[w];
    float inv = 1.f / tot;

    #pragma unroll
    for (int i = 0; i < 8; i++) p[tid + i * 256] = v[i] * inv;
}

// ---------------------------------------------------------------------------
extern "C" void kernel_launch(void* const* d_in, const int* in_sizes, int n_in,
                              void* d_out, int out_size)
{
    const float* pre_q = (const float*)d_in[0];
    const float* pre_k = (const float*)d_in[1];
    const float* pre_v = (const float*)d_in[2];
    const float* Wq = (const float*)d_in[3];
    const float* bq = (const float*)d_in[4];
    const float* Wk = (const float*)d_in[5];
    const float* bk = (const float*)d_in[6];
    const float* Wv = (const float*)d_in[7];
    const float* bv = (const float*)d_in[8];
    const float* Wo = (const float*)d_in[9];
    const float* bo = (const float*)d_in[10];

    float* proj = (float*)d_out;
    float* attn = proj + PROJ_ELEMS;

    __nv_bfloat16 *preh, *prel, *Wh, *Wl, *Woh, *Wol, *QKVh, *QKVl, *Vth, *Vtl, *Oh, *Ol;
    float* bias3;
    cudaGetSymbolAddress((void**)&preh, g_preh);
    cudaGetSymbolAddress((void**)&prel, g_prel);
    cudaGetSymbolAddress((void**)&Wh, g_Wh);
    cudaGetSymbolAddress((void**)&Wl, g_Wl);
    cudaGetSymbolAddress((void**)&Woh, g_Woh);
    cudaGetSymbolAddress((void**)&Wol, g_Wol);
    cudaGetSymbolAddress((void**)&bias3, g_bias3);
    cudaGetSymbolAddress((void**)&QKVh, g_QKVh);
    cudaGetSymbolAddress((void**)&QKVl, g_QKVl);
    cudaGetSymbolAddress((void**)&Vth, g_Vth);
    cudaGetSymbolAddress((void**)&Vtl, g_Vtl);
    cudaGetSymbolAddress((void**)&Oh, g_Oh);
    cudaGetSymbolAddress((void**)&Ol, g_Ol);

    static bool attr_done = false;
    if (!attr_done) {
        cudaFuncSetAttribute(gemm3<0>, cudaFuncAttributeMaxDynamicSharedMemorySize, 81920);
        cudaFuncSetAttribute(gemm3<1>, cudaFuncAttributeMaxDynamicSharedMemorySize, 81920);
        cudaFuncSetAttribute(gemm_pv3, cudaFuncAttributeMaxDynamicSharedMemorySize, 61440);
        attr_done = true;
    }

    // ---- prep: split inputs/weights to bf16 hi/lo; gather biases ----
    splitk<<<4096, 256>>>((const float4*)pre_q, preh,             prel,             1048576);
    splitk<<<4096, 256>>>((const float4*)pre_k, preh + 4194304,   prel + 4194304,   1048576);
    splitk<<<4096, 256>>>((const float4*)pre_v, preh + 8388608,   prel + 8388608,   1048576);
    splitk<<<1024, 256>>>((const float4*)Wq,    Wh,               Wl,               262144);
    splitk<<<1024, 256>>>((const float4*)Wk,    Wh + 1048576,     Wl + 1048576,     262144);
    splitk<<<1024, 256>>>((const float4*)Wv,    Wh + 2097152,     Wl + 2097152,     262144);
    splitk<<<1024, 256>>>((const float4*)Wo,    Woh,              Wol,              262144);
    biascopy<<<4, 256>>>(bq, bk, bv, bias3);

    // ---- QKV projections (merged z=3): split bf16 outputs ----
    gemm3<1><<<dim3(8, 32, 3), 256, 81920>>>(
        preh, prel, Wh, Wl, bias3, nullptr, QKVh, QKVl,
        4096, 1024, 1024, 1.f, 4194304, 1048576, 4194304, 1024);

    // ---- transpose V per head for the PV GEMM ----
    transposeV<<<dim3(32, 32), 256>>>(QKVh + 8388608, QKVl + 8388608, Vth, Vtl);

    // ---- scores per head: Q @ K^T * 1/8 -> attn (fp32) ----
    gemm3<0><<<dim3(16, 16, 32), 256, 81920>>>(
        QKVh, QKVl, QKVh + 4194304, QKVl + 4194304, nullptr, attn, nullptr, nullptr,
        2048, 2048, 64, 0.125f, HEAD_STRIDE, HEAD_STRIDE, ATTN_STRIDE, 0);

    // ---- softmax (in-place, fp32) ----
    softmax_rows<<<65536, 256>>>(attn);

    // ---- O = attn @ V (3-pass: fp32 P split in-kernel, pre-split V) ----
    gemm_pv3<<<dim3(1, 16, 32), 256, 61440>>>(attn, Vth, Vtl, Oh, Ol);

    // ---- output projection: proj = O @ Wo^T + bo ----
    gemm3<0><<<dim3(8, 32, 1), 256, 81920>>>(
        Oh, Ol, Woh, Wol, bo, proj, nullptr, nullptr,
        4096, 1024, 1024, 1.f, 0, 0, 0, 0);
}